// round 10
// baseline (speedup 1.0000x reference)
#include <cuda_runtime.h>
#include <cstdint>
#include <cstddef>

#define NBLK 1480   // 148 SMs x 10 resident blocks

// Single fused kernel. Phase 1: each block cooperatively builds the Wigner D
// matrices (D1: 16x3x3, D2: 16x5x5) in shared memory — warp w handles
// t = 4w..4w+3, lane = matrix entry (i,j). The chain Za@J@Zb@J@Zg is computed
// as A=J@Zb (sparse col-combine), B=A@J (dense), C=Za@B (sparse row-combine),
// D=C@Zg (sparse col-combine); z-rot sparsity: row i has cos(f_i) at (i,i) and
// sin(f_i) at (i,rev_i), f_i=l-i, degenerating correctly at the center row.
// Phase 2: persistent chunk loop over groups of 4 points with the proven R4
// t-loop body (stage to smem double-buffer, one barrier per t, coalesced
// float4 copy-out).
__global__ __launch_bounds__(128, 10) void fused_kernel(
        const float* __restrict__ feat,
        const float* __restrict__ q,
        const float* __restrict__ J1,
        const float* __restrict__ J2,
        float* __restrict__ out,
        int N, int T) {
    __shared__ float sStage[2816];   // stage buf0 [0,1408), buf1 [1408,2816);
                                     // sF aliases [0,1920); build scratch [1920,2368)
    __shared__ float sD1[144];
    __shared__ float sD2[400];

    const int tid = threadIdx.x;
    const int lane = tid & 31;
    const int warp = tid >> 5;

    // ---------------- Phase 1: cooperative D build ----------------
    {
        float* scrA = sStage + 1920 + warp * 112;
        float* scrB = scrA + 56;
        const int i5 = lane / 5, j5 = lane % 5;
        const int i3 = lane / 3, j3 = lane % 3;

        for (int s = 0; s < 4; s++) {
            const int t = 4 * warp + s;
            if (t >= T) break;
            float qr = __ldg(q + 4 * t + 0), qi = __ldg(q + 4 * t + 1);
            float qj = __ldg(q + 4 * t + 2), qk = __ldg(q + 4 * t + 3);
            float inv = rsqrtf(qr * qr + qi * qi + qj * qj + qk * qk);
            qr *= inv; qi *= inv; qj *= inv; qk *= inv;
            float two_s = 2.0f / (qr * qr + qi * qi + qj * qj + qk * qk);
            float M01 = two_s * (qi * qj - qk * qr);
            float M21 = two_s * (qj * qk + qi * qr);
            float M11 = 1.0f - two_s * (qi * qi + qk * qk);
            float M10 = two_s * (qi * qj + qk * qr);
            float M12 = two_s * (qj * qk - qi * qr);
            float alpha = atan2f(M01, M21);
            float beta  = acosf(fmaxf(-1.0f, fminf(1.0f, M11)));
            float gamma = atan2f(M10, -M12);

            // ---- D2 (5x5), lanes 0..24 ----
            if (lane < 25) {      // A = J2 @ Zb(beta): col-combine
                float fj = (float)(2 - j5);
                scrA[i5 * 5 + j5] =
                    __ldg(J2 + i5 * 5 + j5) * cosf(fj * beta) +
                    __ldg(J2 + i5 * 5 + (4 - j5)) * sinf(-fj * beta);
            }
            __syncwarp();
            if (lane < 25) {      // B = A @ J2: dense
                float B = 0.0f;
#pragma unroll
                for (int k = 0; k < 5; k++)
                    B = fmaf(scrA[i5 * 5 + k], __ldg(J2 + k * 5 + j5), B);
                scrB[i5 * 5 + j5] = B;
            }
            __syncwarp();
            if (lane < 25) {      // C = Za(alpha) @ B: row-combine
                float fi = (float)(2 - i5);
                scrA[i5 * 5 + j5] =
                    cosf(fi * alpha) * scrB[i5 * 5 + j5] +
                    sinf(fi * alpha) * scrB[(4 - i5) * 5 + j5];
            }
            __syncwarp();
            if (lane < 25) {      // D = C @ Zg(gamma): col-combine
                float fj = (float)(2 - j5);
                sD2[t * 25 + lane] =
                    scrA[i5 * 5 + j5] * cosf(fj * gamma) +
                    scrA[i5 * 5 + (4 - j5)] * sinf(-fj * gamma);
            }
            __syncwarp();

            // ---- D1 (3x3), lanes 0..8 (reuse scratch) ----
            if (lane < 9) {
                float fj = (float)(1 - j3);
                scrA[i3 * 3 + j3] =
                    __ldg(J1 + i3 * 3 + j3) * cosf(fj * beta) +
                    __ldg(J1 + i3 * 3 + (2 - j3)) * sinf(-fj * beta);
            }
            __syncwarp();
            if (lane < 9) {
                float B = 0.0f;
#pragma unroll
                for (int k = 0; k < 3; k++)
                    B = fmaf(scrA[i3 * 3 + k], __ldg(J1 + k * 3 + j3), B);
                scrB[i3 * 3 + j3] = B;
            }
            __syncwarp();
            if (lane < 9) {
                float fi = (float)(1 - i3);
                scrA[i3 * 3 + j3] =
                    cosf(fi * alpha) * scrB[i3 * 3 + j3] +
                    sinf(fi * alpha) * scrB[(2 - i3) * 3 + j3];
            }
            __syncwarp();
            if (lane < 9) {
                float fj = (float)(1 - j3);
                sD1[t * 9 + lane] =
                    scrA[i3 * 3 + j3] * cosf(fj * gamma) +
                    scrA[i3 * 3 + (2 - j3)] * sinf(-fj * gamma);
            }
            __syncwarp();
        }
    }
    // sD1/sD2 visibility to all warps is fenced by the in-loop __syncthreads.

    // ---------------- Phase 2: persistent chunk loop ----------------
    const int chunks = N >> 2;
    float* sF = sStage;

    for (int c = blockIdx.x; c < chunks; c += gridDim.x) {
        const int pbase = c * 4;

        __syncthreads();   // prior chunk's copy-outs done before sF overwrite
        {
            const float4* src = reinterpret_cast<const float4*>(feat + (size_t)pbase * 480);
            float4* dst = reinterpret_cast<float4*>(sF);
            for (int x = tid; x < 480; x += 128) dst[x] = __ldcs(src + x);
        }
        __syncthreads();

        // Register gather (compile-time indexing only).
        float4 f0[4];
        float in1[4][3];
        float in2[4][5];
        if (tid < 32) {
#pragma unroll
            for (int pp = 0; pp < 4; pp++)
                f0[pp] = reinterpret_cast<const float4*>(sF + pp * 480)[tid];
        } else if (tid < 96) {
            const int m = tid - 32;
#pragma unroll
            for (int pp = 0; pp < 4; pp++)
#pragma unroll
                for (int b = 0; b < 3; b++)
                    in1[pp][b] = sF[pp * 480 + 128 + 3 * m + b];
        } else {
            const int m = tid - 96;
#pragma unroll
            for (int pp = 0; pp < 4; pp++)
#pragma unroll
                for (int b = 0; b < 5; b++)
                    in2[pp][b] = sF[pp * 480 + 320 + 5 * m + b];
        }
        __syncthreads();   // sF reads done before first stage write

        for (int t = 0; t < T; t++) {
            float* buf = sStage + (t & 1) * 1408;

            if (tid >= 32 && tid < 96) {
                const int m = tid - 32;
                const float* D = sD1 + t * 9;
#pragma unroll
                for (int a = 0; a < 3; a++) {
                    const float d0 = D[a * 3 + 0];
                    const float d1 = D[a * 3 + 1];
                    const float d2 = D[a * 3 + 2];
#pragma unroll
                    for (int pp = 0; pp < 4; pp++)
                        buf[pp * 352 + 3 * m + a] =
                            fmaf(d0, in1[pp][0], fmaf(d1, in1[pp][1], d2 * in1[pp][2]));
                }
            } else if (tid >= 96) {
                const int m = tid - 96;
                const float* D = sD2 + t * 25;
#pragma unroll
                for (int a = 0; a < 5; a++) {
                    const float d0 = D[a * 5 + 0];
                    const float d1 = D[a * 5 + 1];
                    const float d2 = D[a * 5 + 2];
                    const float d3 = D[a * 5 + 3];
                    const float d4 = D[a * 5 + 4];
#pragma unroll
                    for (int pp = 0; pp < 4; pp++) {
                        float s = d0 * in2[pp][0];
                        s = fmaf(d1, in2[pp][1], s);
                        s = fmaf(d2, in2[pp][2], s);
                        s = fmaf(d3, in2[pp][3], s);
                        s = fmaf(d4, in2[pp][4], s);
                        buf[pp * 352 + 192 + 5 * m + a] = s;
                    }
                }
            }
            __syncthreads();
            // One barrier per t is safe with double buffering: writers of
            // buffer (t&1) at iter t+2 passed the barrier of iter t+1, which
            // required every thread to finish its iter-t copy-out.

            float* obase = out + ((size_t)t * N + pbase) * 480;
            if (tid < 32) {
#pragma unroll
                for (int pp = 0; pp < 4; pp++)
                    __stcs(reinterpret_cast<float4*>(obase + pp * 480) + tid, f0[pp]);
            } else {
                for (int x = tid - 32; x < 352; x += 96) {
                    const int pp = x / 88;
                    const int c4 = x - pp * 88;
                    float4 v = reinterpret_cast<const float4*>(buf + pp * 352)[c4];
                    __stcs(reinterpret_cast<float4*>(obase + pp * 480 + 128) + c4, v);
                }
            }
        }
    }
}

extern "C" void kernel_launch(void* const* d_in, const int* in_sizes, int n_in,
                              void* d_out, int out_size) {
    const float* feat = (const float*)d_in[0];
    const float* q    = (const float*)d_in[1];
    // d_in[2] = J0 (unused: l=0 is a pure broadcast in the reference)
    const float* J1   = (const float*)d_in[3];
    const float* J2   = (const float*)d_in[4];
    float* out = (float*)d_out;

    const int T = in_sizes[1] / 4;     // 16
    const int N = in_sizes[0] / 480;   // 16384

    const int chunks = N / 4;
    const int grid = (chunks < NBLK) ? chunks : NBLK;
    fused_kernel<<<grid, 128>>>(feat, q, J1, J2, out, N, T);
}

// round 11
// speedup vs baseline: 1.1386x; 1.1386x over previous
#include <cuda_runtime.h>
#include <cstdint>
#include <cstddef>

// Wigner D matrices per quaternion: D1 = 3x3 (l=1), D2 = 5x5 (l=2).
__device__ float g_D1[16 * 9];
__device__ float g_D2[16 * 25];

// Templated (compile-time d) z-rotation build — fully unrolled, stays in regs.
// Reference order: sin on anti-diagonal first, then cos on diagonal.
template <int D>
__device__ __forceinline__ void zrotT(float ang, float* M) {
#pragma unroll
    for (int x = 0; x < D * D; x++) M[x] = 0.0f;
    const int L = (D - 1) / 2;
#pragma unroll
    for (int i = 0; i < D; i++) {
        float f = (float)(L - i);
        M[i * D + (D - 1 - i)] = sinf(f * ang);
        M[i * D + i]           = cosf(f * ang);
    }
}

template <int D>
__device__ __forceinline__ void matmulT(const float* A, const float* B, float* C) {
#pragma unroll
    for (int i = 0; i < D; i++)
#pragma unroll
        for (int j = 0; j < D; j++) {
            float s = 0.0f;
#pragma unroll
            for (int k = 0; k < D; k++) s = fmaf(A[i * D + k], B[k * D + j], s);
            C[i * D + j] = s;
        }
}

// 32 threads: tid 0..15 build D1 for quat tid; tid 16..31 build D2 for quat tid-16.
__global__ void setup_kernel(const float* __restrict__ q,
                             const float* __restrict__ J1,
                             const float* __restrict__ J2,
                             int T) {
    const int tid = threadIdx.x;
    const int t = tid & 15;
    if (t >= T) return;

    float r = q[4 * t + 0], i = q[4 * t + 1], j = q[4 * t + 2], k = q[4 * t + 3];
    float inv = rsqrtf(r * r + i * i + j * j + k * k);
    r *= inv; i *= inv; j *= inv; k *= inv;
    float two_s = 2.0f / (r * r + i * i + j * j + k * k);

    float M01 = two_s * (i * j - k * r);
    float M21 = two_s * (j * k + i * r);
    float M11 = 1.0f - two_s * (i * i + k * k);
    float M10 = two_s * (i * j + k * r);
    float M12 = two_s * (j * k - i * r);

    float alpha = atan2f(M01, M21);
    float beta  = acosf(fmaxf(-1.0f, fminf(1.0f, M11)));
    float gamma = atan2f(M10, -M12);

    if (tid < 16) {
        float Za[9], Zb[9], Zg[9], t1[9], t2[9];
        zrotT<3>(alpha, Za); zrotT<3>(beta, Zb); zrotT<3>(gamma, Zg);
        float Jl[9];
#pragma unroll
        for (int x = 0; x < 9; x++) Jl[x] = J1[x];
        matmulT<3>(Za, Jl, t1);
        matmulT<3>(t1, Zb, t2);
        matmulT<3>(t2, Jl, t1);
        matmulT<3>(t1, Zg, t2);
#pragma unroll
        for (int x = 0; x < 9; x++) g_D1[t * 9 + x] = t2[x];
    } else {
        float Za[25], Zb[25], Zg[25], t1[25], t2[25];
        zrotT<5>(alpha, Za); zrotT<5>(beta, Zb); zrotT<5>(gamma, Zg);
        float Jl[25];
#pragma unroll
        for (int x = 0; x < 25; x++) Jl[x] = J2[x];
        matmulT<5>(Za, Jl, t1);
        matmulT<5>(t1, Zb, t2);
        matmulT<5>(t2, Jl, t1);
        matmulT<5>(t1, Zg, t2);
#pragma unroll
        for (int x = 0; x < 25; x++) g_D2[t * 25 + x] = t2[x];
    }
}

// One block per 4 points. 128 threads (R4-proven body, unchanged):
//   tid 0..31  : l=0, hold 4 points' float4 chunks in regs, store directly.
//   tid 32..95 : l=1, thread owns m=tid-32, 4 points' triples in regs.
//   tid 96..127: l=2, thread owns m=tid-96, 4 points' quintets in regs.
// Per t: broadcast-read D rows from smem once, reuse across 4 points. Stage
// l1/l2 outputs in double-buffered smem (stride 3/5 STS = conflict-free), one
// barrier per t, then coalesced float4 copy-out. All register indexing
// compile-time -> no local-memory spills.
__global__ __launch_bounds__(128) void transform_kernel(
        const float* __restrict__ feat,
        float* __restrict__ out,
        int N, int T) {
    __shared__ float sStage[2][1408];   // 4 points x 352 staged channels, x2 buffers
    __shared__ float sD1[144];
    __shared__ float sD2[400];

    const int tid = threadIdx.x;
    const int pbase = blockIdx.x * 4;

    for (int x = tid; x < 144; x += 128) sD1[x] = g_D1[x];
    for (int x = tid; x < 400; x += 128) sD2[x] = g_D2[x];

    // Coalesced load of 4 points' features into smem (aliases the stage
    // buffers: 1920 floats needed <= 2816 available; barrier below separates).
    float* sF = &sStage[0][0];
    {
        const float4* src = reinterpret_cast<const float4*>(feat + (size_t)pbase * 480);
        float4* dst = reinterpret_cast<float4*>(sF);
        for (int x = tid; x < 480; x += 128) dst[x] = src[x];
    }
    __syncthreads();

    // Register gather (all indices compile-time after unrolling).
    float4 f0[4];
    float in1[4][3];
    float in2[4][5];
    if (tid < 32) {
#pragma unroll
        for (int pp = 0; pp < 4; pp++)
            f0[pp] = reinterpret_cast<const float4*>(sF + pp * 480)[tid];
    } else if (tid < 96) {
        const int m = tid - 32;
#pragma unroll
        for (int pp = 0; pp < 4; pp++)
#pragma unroll
            for (int b = 0; b < 3; b++)
                in1[pp][b] = sF[pp * 480 + 128 + 3 * m + b];
    } else {
        const int m = tid - 96;
#pragma unroll
        for (int pp = 0; pp < 4; pp++)
#pragma unroll
            for (int b = 0; b < 5; b++)
                in2[pp][b] = sF[pp * 480 + 320 + 5 * m + b];
    }
    __syncthreads();   // done reading sF before first stage write

    for (int t = 0; t < T; t++) {
        float* buf = sStage[t & 1];

        if (tid >= 32 && tid < 96) {
            const int m = tid - 32;
            const float* D = sD1 + t * 9;
#pragma unroll
            for (int a = 0; a < 3; a++) {
                const float d0 = D[a * 3 + 0];
                const float d1 = D[a * 3 + 1];
                const float d2 = D[a * 3 + 2];
#pragma unroll
                for (int pp = 0; pp < 4; pp++)
                    buf[pp * 352 + 3 * m + a] =
                        fmaf(d0, in1[pp][0], fmaf(d1, in1[pp][1], d2 * in1[pp][2]));
            }
        } else if (tid >= 96) {
            const int m = tid - 96;
            const float* D = sD2 + t * 25;
#pragma unroll
            for (int a = 0; a < 5; a++) {
                const float d0 = D[a * 5 + 0];
                const float d1 = D[a * 5 + 1];
                const float d2 = D[a * 5 + 2];
                const float d3 = D[a * 5 + 3];
                const float d4 = D[a * 5 + 4];
#pragma unroll
                for (int pp = 0; pp < 4; pp++) {
                    float s = d0 * in2[pp][0];
                    s = fmaf(d1, in2[pp][1], s);
                    s = fmaf(d2, in2[pp][2], s);
                    s = fmaf(d3, in2[pp][3], s);
                    s = fmaf(d4, in2[pp][4], s);
                    buf[pp * 352 + 192 + 5 * m + a] = s;
                }
            }
        }
        __syncthreads();
        // Single barrier per t is safe with double buffering: a thread reaches
        // the stage-write of iter t+2 (same buffer as t) only after passing the
        // barrier of iter t+1, which requires ALL threads to have finished
        // their iter-t copy-out.

        float* obase = out + ((size_t)t * N + pbase) * 480;
        if (tid < 32) {
#pragma unroll
            for (int pp = 0; pp < 4; pp++)
                reinterpret_cast<float4*>(obase + pp * 480)[tid] = f0[pp];
        } else {
            // 352 staged float4 chunks distributed over 96 threads.
            for (int x = tid - 32; x < 352; x += 96) {
                const int pp = x / 88;
                const int c4 = x - pp * 88;
                float4 v = reinterpret_cast<const float4*>(buf + pp * 352)[c4];
                reinterpret_cast<float4*>(obase + pp * 480 + 128)[c4] = v;
            }
        }
    }
}

extern "C" void kernel_launch(void* const* d_in, const int* in_sizes, int n_in,
                              void* d_out, int out_size) {
    const float* feat = (const float*)d_in[0];
    const float* q    = (const float*)d_in[1];
    // d_in[2] = J0 (unused: l=0 is a pure broadcast in the reference)
    const float* J1   = (const float*)d_in[3];
    const float* J2   = (const float*)d_in[4];
    float* out = (float*)d_out;

    const int T = in_sizes[1] / 4;     // 16
    const int N = in_sizes[0] / 480;   // 16384

    setup_kernel<<<1, 32>>>(q, J1, J2, T);
    transform_kernel<<<N / 4, 128>>>(feat, out, N, T);
}